// round 17
// baseline (speedup 1.0000x reference)
#include <cuda_runtime.h>
#include <cuda_fp16.h>
#include <cstdint>

#define B_ 8
#define C_ 256
#define N_ 4096
#define K_ 64
#define MT 64
#define LOG2E 1.4426950408889634f

// g_F: fp16 HI ONLY, tg-major rows of 32 u32.
// g_G: fp16 hi/lo interleaved, permuted rows of 64 u32 (pre-scaled by log2e).
// g_H: fp16 single, transposed [b][d][m-pairs], permuted per 8-pair block.
__device__ uint32_t g_F[(size_t)B_ * N_ * 32];
__device__ uint32_t g_G[(size_t)B_ * N_ * 64];
__device__ uint16_t g_H[(size_t)B_ * C_ * N_];

// ---------------- helpers ----------------
__device__ __forceinline__ uint32_t f16x2(float lo, float hi) {
    uint32_t r;
    asm("cvt.rn.f16x2.f32 %0, %1, %2;" : "=r"(r) : "f"(hi), "f"(lo));
    return r;
}
__device__ __forceinline__ float f16lo(uint32_t p) {
    return __half2float(__ushort_as_half((unsigned short)(p & 0xffffu)));
}
__device__ __forceinline__ float f16hi(uint32_t p) {
    return __half2float(__ushort_as_half((unsigned short)(p >> 16)));
}
__device__ __forceinline__ float ex2(float x) {
    float r; asm("ex2.approx.f32 %0, %1;" : "=f"(r) : "f"(x)); return r;
}
__device__ __forceinline__ void mma_f16(float* c,
    uint32_t a0, uint32_t a1, uint32_t a2, uint32_t a3,
    uint32_t b0, uint32_t b1) {
    asm volatile("mma.sync.aligned.m16n8k16.row.col.f32.f16.f16.f32 "
        "{%0,%1,%2,%3},{%4,%5,%6,%7},{%8,%9},{%0,%1,%2,%3};"
        : "+f"(c[0]), "+f"(c[1]), "+f"(c[2]), "+f"(c[3])
        : "r"(a0), "r"(a1), "r"(a2), "r"(a3), "r"(b0), "r"(b1));
}
__device__ __forceinline__ void cp16(uint32_t dst, const void* src) {
    asm volatile("cp.async.cg.shared.global [%0], [%1], 16;" :: "r"(dst), "l"(src));
}
__device__ __forceinline__ void cp_commit() { asm volatile("cp.async.commit_group;"); }
__device__ __forceinline__ void cp_wait0()  { asm volatile("cp.async.wait_group 0;"); }

__device__ __forceinline__ int pair_off(int p) {
    int qb = p & 7;
    return (p >> 3) * 16 + ((qb & 3) * 2 + (qb >> 2)) * 2;
}

// ---------------------------------------------------------------------------
// Tensor-core projection, H row-groups merged (feat staged/converted ONCE
// per CTA for both H halves). grid (32, 2, B): rg=0 FG, rg=1 H[0:256).
// Per-output MMA math identical to round 15 -> outputs bit-identical.
// ---------------------------------------------------------------------------
#define PGROW 80
#define PSMEMB (2 * 128 * PGROW * 4)     // 81920 B

__global__ __launch_bounds__(256, 2) void proj_kernel(
    const float* __restrict__ feat,
    const float* __restrict__ WF,
    const float* __restrict__ WG,
    const float* __restrict__ WH)
{
    extern __shared__ uint32_t psm[];
    uint32_t* sA = psm;                  // W rows
    uint32_t* sB = psm + 128 * PGROW;    // feat rows (B for H) / A for FG

    const int tid  = threadIdx.x;
    const int lane = tid & 31;
    const int w    = tid >> 5;
    const int gr   = lane >> 2;
    const int tg   = lane & 3;
    const int nb0  = blockIdx.x * 128;
    const int rg   = blockIdx.y;
    const int b    = blockIdx.z;
    const bool modeH = (rg > 0);
    const float* fb = feat + (size_t)b * C_ * N_;

    float acc[32][4];
    const int nacc = modeH ? 32 : 16;
#pragma unroll
    for (int i = 0; i < 32; i++) {
        acc[i][0] = 0.f; acc[i][1] = 0.f; acc[i][2] = 0.f; acc[i][3] = 0.f;
    }

#pragma unroll 1
    for (int kt = 0; kt < 4; kt++) {
        const int c0 = kt * 64;
        __syncthreads();

        {   // stage feat tile ONCE (sB for H-mode B-operand; sB also used
            // as FG A-operand — unified: FG reads A from sB, W from sA)
            const int n_i  = tid & 127;
            const int half = tid >> 7;
            uint32_t* row = sB + n_i * PGROW;
            const float* fp = fb + (size_t)(c0 + half * 32) * N_ + nb0 + n_i;
#pragma unroll
            for (int p = 0; p < 16; p++) {
                float x0 = fp[(size_t)(2 * p) * N_];
                float x1 = fp[(size_t)(2 * p + 1) * N_];
                uint32_t hi2 = f16x2(x0, x1);
                uint32_t lo2 = f16x2(x0 - f16lo(hi2), x1 - f16hi(hi2));
                uint2 o; o.x = hi2; o.y = lo2;
                *(uint2*)(row + pair_off(half * 16 + p)) = o;
            }
        }
#pragma unroll 1
        for (int ph = 0; ph < (modeH ? 2 : 1); ph++) {
            if (ph == 1) __syncthreads();      // sA consumers (phase 0) done
            {   // stage W tile (linear float4): FG=[WF;WG], H=WH[ph*128 ..)
#pragma unroll
                for (int i = 0; i < 8; i++) {
                    const int idx = tid + i * 256;
                    const int r = idx >> 4, f4 = idx & 15;
                    const float* Wr;
                    if (modeH) Wr = WH + (size_t)(ph * 128 + r) * C_;
                    else       Wr = (r < 64) ? WF + (size_t)r * C_
                                             : WG + (size_t)(r - 64) * C_;
                    float4 x = __ldg((const float4*)(Wr + c0 + f4 * 4));
                    uint32_t h0 = f16x2(x.x, x.y);
                    uint32_t l0 = f16x2(x.x - f16lo(h0), x.y - f16hi(h0));
                    uint32_t h1 = f16x2(x.z, x.w);
                    uint32_t l1 = f16x2(x.z - f16lo(h1), x.w - f16hi(h1));
                    uint32_t* row = sA + r * PGROW;
                    uint2 o0; o0.x = h0; o0.y = l0;
                    uint2 o1; o1.x = h1; o1.y = l1;
                    *(uint2*)(row + pair_off(2 * f4))     = o0;
                    *(uint2*)(row + pair_off(2 * f4 + 1)) = o1;
                }
            }
            __syncthreads();

            // A rows: FG -> feat (sB), H -> WH (sA). B: the other buffer.
            const uint32_t* Asrc = modeH ? sA : sB;
            const uint32_t* Bsrc = modeH ? sB : sA;
            float (*ac)[4] = acc + ph * 16;
            const uint32_t* ga = Asrc + (w * 16 + gr) * PGROW;
#pragma unroll
            for (int kc = 0; kc < 4; kc++) {
                const int o0 = kc * 16 + 4 * tg;
                uint4 Aa = *(const uint4*)(ga + o0);
                uint4 Ab = *(const uint4*)(ga + 8 * PGROW + o0);
#pragma unroll
                for (int t8 = 0; t8 < 16; t8++) {
                    const uint32_t* f = Bsrc + (t8 * 8 + gr) * PGROW + o0;
                    uint4 Bv = *(const uint4*)f;
                    mma_f16(ac[t8], Aa.x, Ab.x, Aa.z, Ab.z, Bv.x, Bv.z);
                    mma_f16(ac[t8], Aa.x, Ab.x, Aa.z, Ab.z, Bv.y, Bv.w);
                    mma_f16(ac[t8], Aa.y, Ab.y, Aa.w, Ab.w, Bv.x, Bv.z);
                }
            }
        }
    }
    __syncthreads();

    if (!modeH) {
        uint32_t* psF = psm;                     // 128*36
        uint32_t* psG = psm + 4608;              // 128*68
        const int nloc0 = w * 16 + gr;
#pragma unroll
        for (int t8 = 0; t8 < 16; t8++) {
            if (t8 < 8) {
                const int pos = tg * 8 + (t8 >> 1) * 2 + (t8 & 1);
#pragma unroll
                for (int h = 0; h < 2; h++) {
                    uint32_t hi2 = f16x2(acc[t8][2 * h], acc[t8][2 * h + 1]);
                    psF[(nloc0 + h * 8) * 36 + pos] = hi2;
                }
            } else {
                const int off = pair_off((t8 - 8) * 4 + tg);
#pragma unroll
                for (int h = 0; h < 2; h++) {
                    float v0 = acc[t8][2 * h] * LOG2E;
                    float v1 = acc[t8][2 * h + 1] * LOG2E;
                    uint32_t hi2 = f16x2(v0, v1);
                    uint32_t lo2 = f16x2(v0 - f16lo(hi2), v1 - f16hi(hi2));
                    uint2 o; o.x = hi2; o.y = lo2;
                    *(uint2*)(psG + (nloc0 + h * 8) * 68 + off) = o;
                }
            }
        }
        __syncthreads();
#pragma unroll
        for (int i = 0; i < 4; i++) {
            const int idx = tid + i * 256;
            const int row = idx >> 3, q4 = idx & 7;
            uint4 v = *(const uint4*)(psF + row * 36 + q4 * 4);
            *(uint4*)(g_F + ((size_t)b * N_ + nb0 + row) * 32 + q4 * 4) = v;
        }
#pragma unroll
        for (int i = 0; i < 8; i++) {
            const int idx = tid + i * 256;
            const int row = idx >> 4, q4 = idx & 15;
            uint4 v = *(const uint4*)(psG + row * 68 + q4 * 4);
            *(uint4*)(g_G + ((size_t)b * N_ + nb0 + row) * 64 + q4 * 4) = v;
        }
    } else {
        // stage BOTH H halves: 256 rows x 68 u32 = 17408 <= 20480 available
        const int dl = w * 16 + gr;
#pragma unroll
        for (int ph = 0; ph < 2; ph++) {
            float (*ac)[4] = acc + ph * 16;
            const int dloc0 = ph * 128 + dl;
#pragma unroll
            for (int nt = 0; nt < 16; nt++) {
                const int Pl = nt * 4 + tg;
                const int qb = Pl & 7;
                const int posl = (Pl & ~15) + ((Pl >> 3) & 1) * 8
                               + (qb & 3) * 2 + (qb >> 2);
                psm[dloc0 * 68 + posl]       = f16x2(ac[nt][0], ac[nt][1]);
                psm[(dloc0 + 8) * 68 + posl] = f16x2(ac[nt][2], ac[nt][3]);
            }
        }
        __syncthreads();
        uint32_t* Hb = (uint32_t*)g_H + (size_t)b * C_ * 2048;
#pragma unroll
        for (int i = 0; i < 16; i++) {
            const int idx = tid + i * 256;             // 0..4095
            const int row = idx >> 4, q4 = idx & 15;   // row = d 0..255
            uint4 v = *(const uint4*)(psm + row * 68 + q4 * 4);
            *(uint4*)(Hb + (size_t)row * 2048 + nb0 / 2 + q4 * 4) = v;
        }
    }
}

// ---------------------------------------------------------------------------
// fp16 flash attention — UNCHANGED from round 15 (329 us, rel_err 3.611e-4).
// MT=64, S 2-pass (Gh+Gl).Fh, PV 1-pass fp16, 256 thr, 128 q-rows.
// ---------------------------------------------------------------------------
#define GROW 80
#define FROW 36
#define HROW 40
#define SG  0
#define SF  (128 * GROW)                 // 10240
#define FPL (MT * FROW)                  // 2304
#define SH  (SF + 2 * FPL)               // 14848
#define HPL (C_ * HROW)                  // 10240
#define SMEMU (SH + 2 * HPL)             // 35328 u32
#define SMEMB (SMEMU * 4)                // 141312 B

__global__ __launch_bounds__(256, 1) void attn_kernel(
    const float* __restrict__ input,
    const float* __restrict__ gamma_p,
    float* __restrict__ out)
{
    extern __shared__ uint32_t sm[];
    uint32_t smu;
    asm("{ .reg .u64 t; cvta.to.shared.u64 t, %1; cvt.u32.u64 %0, t; }"
        : "=r"(smu) : "l"(sm));

    const int tid  = threadIdx.x;
    const int lane = tid & 31;
    const int w    = tid >> 5;
    const int gr   = lane >> 2;
    const int tg   = lane & 3;
    const int n0   = blockIdx.x * 128;
    const int b    = blockIdx.y;

    const uint32_t* FG = g_F + (size_t)b * N_ * 32;
    const uint32_t* HG = (const uint32_t*)(g_H + (size_t)b * C_ * N_);

    {
        const uint32_t* GG = g_G + ((size_t)b * N_ + n0) * 64;
        for (int i = tid; i < 128 * 16; i += 256) {
            int r = i >> 4, ch = i & 15;
            cp16(smu + (SG + r * GROW + ch * 4) * 4, GG + r * 64 + ch * 4);
        }
    }
    {
        for (int i = tid; i < 512; i += 256) {
            int r = i >> 3, ch = i & 7;
            cp16(smu + (SF + r * FROW + ch * 4) * 4, FG + (size_t)r * 32 + ch * 4);
        }
        for (int i = tid; i < 2048; i += 256) {
            int r = i >> 3, ch = i & 7;
            cp16(smu + (SH + r * HROW + ch * 4) * 4, HG + (size_t)r * 2048 + ch * 4);
        }
        cp_commit();
    }

    float oacc[32][4];
#pragma unroll
    for (int i = 0; i < 32; i++) {
        oacc[i][0] = 0.f; oacc[i][1] = 0.f; oacc[i][2] = 0.f; oacc[i][3] = 0.f;
    }
    const float NEG_INF = __int_as_float(0xff800000);
    float mrow0 = NEG_INF, mrow1 = NEG_INF, lsum0 = 0.f, lsum1 = 0.f;

    const uint32_t* g0 = sm + SG + (w * 16 + gr) * GROW;

#pragma unroll 1
    for (int t = 0; t < N_ / MT; t++) {
        cp_wait0();
        __syncthreads();

        const int cur = t & 1;
        if (t + 1 < N_ / MT) {
            const int m0n = (t + 1) * MT;
            const int nb = cur ^ 1;
            for (int i = tid; i < 512; i += 256) {
                int r = i >> 3, ch = i & 7;
                cp16(smu + (SF + nb * FPL + r * FROW + ch * 4) * 4,
                     FG + (size_t)(m0n + r) * 32 + ch * 4);
            }
            for (int i = tid; i < 2048; i += 256) {
                int r = i >> 3, ch = i & 7;
                cp16(smu + (SH + nb * HPL + r * HROW + ch * 4) * 4,
                     HG + (size_t)r * 2048 + m0n / 2 + ch * 4);
            }
            cp_commit();
        }

        const uint32_t* sFc = sm + SF + cur * FPL;
        const uint32_t* sHc = sm + SH + cur * HPL;

        float sc[8][4];
#pragma unroll
        for (int ms = 0; ms < 8; ms++) {
            sc[ms][0] = 0.f; sc[ms][1] = 0.f; sc[ms][2] = 0.f; sc[ms][3] = 0.f;
        }
#pragma unroll
        for (int kh = 0; kh < 2; kh++) {
            const int o0 = (2 * kh) * 16 + 4 * tg;
            const int o1 = (2 * kh + 1) * 16 + 4 * tg;
            uint4 A0a = *(const uint4*)(g0 + o0);
            uint4 A0b = *(const uint4*)(g0 + 8 * GROW + o0);
            uint4 A1a = *(const uint4*)(g0 + o1);
            uint4 A1b = *(const uint4*)(g0 + 8 * GROW + o1);
#pragma unroll
            for (int ms = 0; ms < 8; ms++) {
                const uint32_t* f = sFc + (ms * 8 + gr) * FROW + tg * 8 + kh * 4;
                uint4 Bv = *(const uint4*)f;
                mma_f16(sc[ms], A0a.x, A0b.x, A0a.z, A0b.z, Bv.x, Bv.y);
                mma_f16(sc[ms], A0a.y, A0b.y, A0a.w, A0b.w, Bv.x, Bv.y);
                mma_f16(sc[ms], A1a.x, A1b.x, A1a.z, A1b.z, Bv.z, Bv.w);
                mma_f16(sc[ms], A1a.y, A1b.y, A1a.w, A1b.w, Bv.z, Bv.w);
            }
        }

        float t0 = NEG_INF, t1 = NEG_INF;
#pragma unroll
        for (int ms = 0; ms < 8; ms++) {
            t0 = fmaxf(t0, fmaxf(sc[ms][0], sc[ms][1]));
            t1 = fmaxf(t1, fmaxf(sc[ms][2], sc[ms][3]));
        }
        t0 = fmaxf(t0, __shfl_xor_sync(0xffffffffu, t0, 1));
        t0 = fmaxf(t0, __shfl_xor_sync(0xffffffffu, t0, 2));
        t1 = fmaxf(t1, __shfl_xor_sync(0xffffffffu, t1, 1));
        t1 = fmaxf(t1, __shfl_xor_sync(0xffffffffu, t1, 2));

        const float mn0 = fmaxf(mrow0, t0);
        const float mn1 = fmaxf(mrow1, t1);
        const bool up = (mn0 != mrow0) || (mn1 != mrow1);
        if (__any_sync(0xffffffffu, up)) {
            const float cr0 = ex2(mrow0 - mn0);
            const float cr1 = ex2(mrow1 - mn1);
            lsum0 *= cr0; lsum1 *= cr1;
#pragma unroll
            for (int dt = 0; dt < 32; dt++) {
                oacc[dt][0] *= cr0; oacc[dt][1] *= cr0;
                oacc[dt][2] *= cr1; oacc[dt][3] *= cr1;
            }
            mrow0 = mn0; mrow1 = mn1;
        }
#pragma unroll
        for (int ms = 0; ms < 8; ms++) {
            sc[ms][0] = ex2(sc[ms][0] - mrow0);
            sc[ms][1] = ex2(sc[ms][1] - mrow0);
            sc[ms][2] = ex2(sc[ms][2] - mrow1);
            sc[ms][3] = ex2(sc[ms][3] - mrow1);
            lsum0 += sc[ms][0] + sc[ms][1];
            lsum1 += sc[ms][2] + sc[ms][3];
        }

#pragma unroll
        for (int j = 0; j < 4; j++) {
            const float* cA = sc[2 * j];
            const float* cB = sc[2 * j + 1];
            uint32_t p0 = f16x2(cA[0], cA[1]);
            uint32_t p1 = f16x2(cA[2], cA[3]);
            uint32_t p2 = f16x2(cB[0], cB[1]);
            uint32_t p3 = f16x2(cB[2], cB[3]);
            const uint32_t* hb = sHc + gr * HROW + j * 8 + 2 * tg;
#pragma unroll
            for (int dt = 0; dt < 32; dt++) {
                uint2 bv = *(const uint2*)(hb + dt * 8 * HROW);
                mma_f16(oacc[dt], p0, p1, p2, p3, bv.x, bv.y);
            }
        }
    }

    lsum0 += __shfl_xor_sync(0xffffffffu, lsum0, 1);
    lsum0 += __shfl_xor_sync(0xffffffffu, lsum0, 2);
    lsum1 += __shfl_xor_sync(0xffffffffu, lsum1, 1);
    lsum1 += __shfl_xor_sync(0xffffffffu, lsum1, 2);
    const float inv0 = 1.0f / lsum0;
    const float inv1 = 1.0f / lsum1;
    const float gm = __ldg(gamma_p);

    const int r0 = n0 + w * 16 + gr;
    const int r1 = r0 + 8;
    const size_t base0 = ((size_t)b * N_ + r0) * C_ + tg * 2;
    const size_t base1 = ((size_t)b * N_ + r1) * C_ + tg * 2;
#pragma unroll
    for (int dt = 0; dt < 32; dt++) {
        float2 iv0 = *(const float2*)(input + base0 + dt * 8);
        float2 iv1 = *(const float2*)(input + base1 + dt * 8);
        float2 ov0, ov1;
        ov0.x = fmaf(gm, oacc[dt][0] * inv0, iv0.x);
        ov0.y = fmaf(gm, oacc[dt][1] * inv0, iv0.y);
        ov1.x = fmaf(gm, oacc[dt][2] * inv1, iv1.x);
        ov1.y = fmaf(gm, oacc[dt][3] * inv1, iv1.y);
        *(float2*)(out + base0 + dt * 8) = ov0;
        *(float2*)(out + base1 + dt * 8) = ov1;
    }
}

// ---------------------------------------------------------------------------
extern "C" void kernel_launch(void* const* d_in, const int* in_sizes, int n_in,
                              void* d_out, int out_size) {
    (void)in_sizes; (void)n_in; (void)out_size;
    const float* input = (const float*)d_in[0];
    const float* feat  = (const float*)d_in[1];   // nms_feat
    const float* WF    = (const float*)d_in[2];
    const float* WG    = (const float*)d_in[3];
    const float* WH    = (const float*)d_in[4];
    const float* gamma = (const float*)d_in[5];
    float* out = (float*)d_out;

    cudaFuncSetAttribute(proj_kernel,
                         cudaFuncAttributeMaxDynamicSharedMemorySize, PSMEMB);
    cudaFuncSetAttribute(attn_kernel,
                         cudaFuncAttributeMaxDynamicSharedMemorySize, SMEMB);

    proj_kernel<<<dim3(N_ / 128, 2, B_), 256, PSMEMB>>>(feat, WF, WG, WH);
    attn_kernel<<<dim3(N_ / 128, B_), 256, SMEMB>>>(input, gamma, out);
}